// round 10
// baseline (speedup 1.0000x reference)
#include <cuda_runtime.h>
#include <cuda_fp16.h>
#include <math.h>
#include <stdint.h>

#define BATCH 8
#define CDIM 192
#define C3 576
#define HEADS 8
#define CHH 24
#define NPIX 16384
#define IMW 128

// ---------------- scratch (device globals; allocation-free rule) ------------
__device__ float g_qkv1[BATCH * C3 * NPIX];
__device__ float g_qkv2[BATCH * C3 * NPIX];
__device__ float g_gram[BATCH * HEADS * CHH * CHH];
__device__ float g_nq[BATCH * CDIM];
__device__ float g_nk[BATCH * CDIM];
__device__ __half g_wq[C3 * CDIM];
__device__ __half g_weff[BATCH * CDIM * CDIM];

#define MMA_F16(d, a, bb) \
    asm volatile("mma.sync.aligned.m16n8k16.row.col.f32.f16.f16.f32 " \
        "{%0,%1,%2,%3}, {%4,%5,%6,%7}, {%8,%9}, {%0,%1,%2,%3};" \
        : "+f"((d)[0]), "+f"((d)[1]), "+f"((d)[2]), "+f"((d)[3]) \
        : "r"((a)[0]), "r"((a)[1]), "r"((a)[2]), "r"((a)[3]), \
          "r"((bb)[0]), "r"((bb)[1]))

#define LDSM_X4(r0, r1, r2, r3, addr) \
    asm volatile("ldmatrix.sync.aligned.m8n8.x4.shared.b16 {%0,%1,%2,%3}, [%4];" \
        : "=r"(r0), "=r"(r1), "=r"(r2), "=r"(r3) : "r"(addr))

__device__ __forceinline__ uint32_t pack_h2(__half a, __half b) {
    return ((uint32_t)__half_as_ushort(b) << 16) | __half_as_ushort(a);
}
__device__ __forceinline__ uint32_t smem_u32(const void* p) {
    uint32_t a;
    asm("{ .reg .u64 t; cvta.to.shared.u64 t, %1; cvt.u32.u64 %0, t; }"
        : "=r"(a) : "l"(p));
    return a;
}
__device__ __forceinline__ void cp_async16(uint32_t dst, const void* src) {
    asm volatile("cp.async.cg.shared.global [%0], [%1], 16;" :: "r"(dst), "l"(src));
}

// ---------------------------------------------------------------------------
// HMMA GEMM: Y[o,n] = sum_c W[o,c] X[c,n] per batch, single fp16 pass.
// BM=192, BN=64 x NT=4 tiles per block, BK=32, K=192. 256 threads (8 warps:
// 4M x 2N; 48x32/warp), 2 CTAs/SM. A panel loaded ONCE per block (cp.async),
// then 24 ring-buffered k-iterations sweep 4 n-tiles; epilogue from regs.
// ---------------------------------------------------------------------------
#define NT 4
#define LDAE 200                       // A row stride (halves)
#define LDB  40                        // B row stride (halves)
#define B0_OFF  (192 * LDAE * 2)       // bytes: B buffer 0 (76800)
#define BBUF_BYTES (64 * LDB * 2)      // 5120
#define SMEM_GEMM (B0_OFF + 2 * BBUF_BYTES)   // 87040 bytes

__global__ __launch_bounds__(256, 2)
void gemm_mma(const __half* __restrict__ W, long long wstride,
              const float* __restrict__ X, long long xstride,
              float* __restrict__ Y, long long ystride)
{
    extern __shared__ __half smem[];
    __half* Ah = smem;
    __half* Bb = reinterpret_cast<__half*>(reinterpret_cast<char*>(smem) + B0_OFF);

    const int b = blockIdx.z;
    const int o0 = blockIdx.x * 192;
    const int n0 = blockIdx.y * (64 * NT);
    const __half* Wp = W + (long long)b * wstride;
    const float* Xp = X + (long long)b * xstride;
    float* Yp = Y + (long long)b * ystride;

    const int tid = threadIdx.x;
    const int lane = tid & 31;
    const int wid = tid >> 5;
    const int wm = wid & 3;            // 4 in M (48 rows each)
    const int wn = wid >> 2;           // 2 in N (32 cols each)

    // ---- async load of full A panel: 192 rows x 192 k (once per block) ----
    {
        const uint32_t ah = smem_u32(Ah);
#pragma unroll
        for (int c = 0; c < 18; ++c) {
            int ch = c * 256 + tid;            // 0..4607
            int row = ch / 24, col = ch % 24;  // 16B chunks (8 halves)
            uint32_t doff = (uint32_t)(row * LDAE + col * 8) * 2u;
            long long soff = (long long)(o0 + row) * CDIM + col * 8;
            cp_async16(ah + doff, Wp + soff);
        }
        asm volatile("cp.async.commit_group;");
    }

    float acc[3][4][4];
#pragma unroll
    for (int mi = 0; mi < 3; ++mi)
#pragma unroll
        for (int ni = 0; ni < 4; ++ni)
#pragma unroll
            for (int q = 0; q < 4; ++q) acc[mi][ni][q] = 0.f;

    // ---- ldmatrix per-lane addresses ----
    const int lg = lane >> 3, lr = lane & 7;
    const uint32_t a_base = smem_u32(Ah);
    const uint32_t b_base = smem_u32(Bb);
    uint32_t a_row[3];
#pragma unroll
    for (int mi = 0; mi < 3; ++mi) {
        int row = wm * 48 + mi * 16 + (lg & 1) * 8 + lr;
        a_row[mi] = a_base + (uint32_t)(row * LDAE + (lg >> 1) * 8) * 2u;
    }
    uint32_t b_row[2];
#pragma unroll
    for (int nj = 0; nj < 2; ++nj) {
        int n = wn * 32 + (nj * 2 + (lg >> 1)) * 8 + lr;
        b_row[nj] = (uint32_t)(n * LDB + (lg & 1) * 8) * 2u;
    }

    // ---- B conversion lane mapping: thread covers k rows {kr,kr+1}, 4 n ----
    const int kr = (tid >> 4) * 2;        // 0..30 even
    const int nc = (tid & 15) * 4;        // n within 64-tile
    float4 pb[2];
#pragma unroll
    for (int r = 0; r < 2; ++r)
        pb[r] = *reinterpret_cast<const float4*>(
            &Xp[(long long)(kr + r) * NPIX + n0 + nc]);

    // prologue: convert iteration-0 tile into buffer 0
    asm volatile("cp.async.wait_group 0;");
    {
        float e0[4] = {pb[0].x, pb[0].y, pb[0].z, pb[0].w};
        float e1[4] = {pb[1].x, pb[1].y, pb[1].z, pb[1].w};
#pragma unroll
        for (int i = 0; i < 4; ++i)
            *reinterpret_cast<uint32_t*>(&Bb[(nc + i) * LDB + kr]) =
                pack_h2(__float2half(e0[i]), __float2half(e1[i]));
    }
    __syncthreads();

    for (int it = 0; it < 6 * NT; ++it) {
        const int kt = it % 6;
        const uint32_t cur_off = (uint32_t)(it & 1) * BBUF_BYTES;
        const uint32_t nxt_off = BBUF_BYTES - cur_off;

        // ---- prefetch next iteration's B slice from gmem ----
        if (it < 6 * NT - 1) {
            const int nit = it + 1;
            const int kk = (nit % 6) * 32;
            const int nn = n0 + (nit / 6) * 64;
#pragma unroll
            for (int r = 0; r < 2; ++r)
                pb[r] = *reinterpret_cast<const float4*>(
                    &Xp[(long long)(kk + kr + r) * NPIX + nn + nc]);
        }

        // ---- compute 2 ksteps from current buffer ----
#pragma unroll
        for (int ks = 0; ks < 2; ++ks) {
            const uint32_t akoff = (uint32_t)(kt * 32 + ks * 16) * 2u;
            const uint32_t bkoff = (uint32_t)(ks * 16) * 2u;
            uint32_t fa[3][4], fb[4][2];
#pragma unroll
            for (int mi = 0; mi < 3; ++mi)
                LDSM_X4(fa[mi][0], fa[mi][1], fa[mi][2], fa[mi][3],
                        a_row[mi] + akoff);
#pragma unroll
            for (int nj = 0; nj < 2; ++nj)
                LDSM_X4(fb[2 * nj][0], fb[2 * nj][1], fb[2 * nj + 1][0], fb[2 * nj + 1][1],
                        b_base + cur_off + b_row[nj] + bkoff);
#pragma unroll
            for (int mi = 0; mi < 3; ++mi)
#pragma unroll
                for (int ni = 0; ni < 4; ++ni)
                    MMA_F16(acc[mi][ni], fa[mi], fb[ni]);
        }

        // ---- convert prefetched slice into the other buffer ----
        if (it < 6 * NT - 1) {
            __half* Bn = reinterpret_cast<__half*>(
                reinterpret_cast<char*>(Bb) + nxt_off);
            float e0[4] = {pb[0].x, pb[0].y, pb[0].z, pb[0].w};
            float e1[4] = {pb[1].x, pb[1].y, pb[1].z, pb[1].w};
#pragma unroll
            for (int i = 0; i < 4; ++i)
                *reinterpret_cast<uint32_t*>(&Bn[(nc + i) * LDB + kr]) =
                    pack_h2(__float2half(e0[i]), __float2half(e1[i]));
        }
        __syncthreads();

        // ---- per-tile epilogue (regs -> gmem, no smem, no sync) ----
        if (kt == 5) {
            const int nb = n0 + (it / 6) * 64;
#pragma unroll
            for (int mi = 0; mi < 3; ++mi) {
                int r = o0 + wm * 48 + mi * 16 + (lane >> 2);
#pragma unroll
                for (int ni = 0; ni < 4; ++ni) {
                    int c = nb + wn * 32 + ni * 8 + (lane & 3) * 2;
                    *reinterpret_cast<float2*>(&Yp[(long long)r * NPIX + c]) =
                        make_float2(acc[mi][ni][0], acc[mi][ni][1]);
                    *reinterpret_cast<float2*>(&Yp[(long long)(r + 8) * NPIX + c]) =
                        make_float2(acc[mi][ni][2], acc[mi][ni][3]);
                    acc[mi][ni][0] = acc[mi][ni][1] = 0.f;
                    acc[mi][ni][2] = acc[mi][ni][3] = 0.f;
                }
            }
        }
    }
}

// ---------------------------------------------------------------------------
// Weight prep: fp32 -> fp16
// ---------------------------------------------------------------------------
__global__ void prep_wqkv_kernel(const float* __restrict__ W, int base)
{
    int idx = base + blockIdx.x * blockDim.x + threadIdx.x;
    if (idx >= C3 * CDIM) return;
    g_wq[idx] = __float2half(W[idx]);
}

// ---------------------------------------------------------------------------
// 3x3 depthwise conv, padding 1; 4 pixels per thread (float4)
// ---------------------------------------------------------------------------
__global__ void dwconv_kernel(const float* __restrict__ in,
                              const float* __restrict__ wdw,
                              float* __restrict__ out)
{
    long long idx = (long long)blockIdx.x * blockDim.x + threadIdx.x;
    if (idx >= (long long)BATCH * C3 * (NPIX / 4)) return;
    const int n4 = (int)(idx & (NPIX / 4 - 1));
    const int ch = (int)(idx >> 12);
    const int oc = ch % C3;
    const int y = n4 >> 5;
    const int x0 = (n4 & 31) * 4;
    const float* w = wdw + oc * 9;
    const float* p = in + (long long)ch * NPIX;

    float4 o = make_float4(0.f, 0.f, 0.f, 0.f);
#pragma unroll
    for (int r = 0; r < 3; ++r) {
        int yy = y + r - 1;
        if (yy < 0 || yy > IMW - 1) continue;
        const float* row = p + yy * IMW;
        float4 c = *reinterpret_cast<const float4*>(&row[x0]);
        float lft = (x0 > 0) ? row[x0 - 1] : 0.f;
        float rgt = (x0 < IMW - 4) ? row[x0 + 4] : 0.f;
        float w0 = w[r * 3], w1 = w[r * 3 + 1], w2 = w[r * 3 + 2];
        o.x += w0 * lft + w1 * c.x + w2 * c.y;
        o.y += w0 * c.x + w1 * c.y + w2 * c.z;
        o.z += w0 * c.y + w1 * c.z + w2 * c.w;
        o.w += w0 * c.z + w1 * c.w + w2 * rgt;
    }
    *reinterpret_cast<float4*>(&out[(long long)ch * NPIX + y * IMW + x0]) = o;
}

__global__ void zero_misc_kernel()
{
    int i = blockIdx.x * blockDim.x + threadIdx.x;
    if (i < BATCH * HEADS * CHH * CHH) g_gram[i] = 0.f;
    if (i < BATCH * CDIM) { g_nq[i] = 0.f; g_nk[i] = 0.f; }
}

// ---------------------------------------------------------------------------
// Gram + fused norms
// ---------------------------------------------------------------------------
__global__ void gram_kernel(const float* __restrict__ feat)
{
    __shared__ float QF[4][CHH][64];
    __shared__ float KF[4][CHH][64];

    const int bh = blockIdx.y;
    const int b = bh >> 3, hd = bh & 7;
    const int n0 = blockIdx.x * 1024;
    const int t = threadIdx.x;
    const int g = t >> 6, l = t & 63;
    const int li = l >> 3, lj = l & 7;
    const int i0 = li * 3, j0 = lj * 3;

    const float* qbase = g_qkv2 + ((long long)b * C3 + hd * CHH) * NPIX;
    const float* kbase = g_qkv2 + ((long long)b * C3 + CDIM + hd * CHH) * NPIX;
    const float* fbase = feat + ((long long)b * CDIM + hd * CHH) * NPIX;

    float acc[3][3];
#pragma unroll
    for (int a = 0; a < 3; ++a)
#pragma unroll
        for (int cc = 0; cc < 3; ++cc) acc[a][cc] = 0.f;
    float nqp = 0.f, nkp = 0.f;

    for (int s = 0; s < 1024; s += 256) {
        const int nb = n0 + s + g * 64;
        for (int e = l; e < CHH * 64; e += 64) {
            int i = e >> 6, nn = e & 63;
            long long off = (long long)i * NPIX + nb + nn;
            float fv = fbase[off];
            QF[g][i][nn] = qbase[off] * fv;
            KF[g][i][nn] = kbase[off] * fv;
        }
        __syncthreads();
#pragma unroll 4
        for (int it = 0; it < 64; ++it) {
            int nn = (it + l) & 63;
            float q0 = QF[g][i0 + 0][nn];
            float q1 = QF[g][i0 + 1][nn];
            float q2 = QF[g][i0 + 2][nn];
            float k0 = KF[g][j0 + 0][nn];
            float k1 = KF[g][j0 + 1][nn];
            float k2 = KF[g][j0 + 2][nn];
            acc[0][0] += q0 * k0; acc[0][1] += q0 * k1; acc[0][2] += q0 * k2;
            acc[1][0] += q1 * k0; acc[1][1] += q1 * k1; acc[1][2] += q1 * k2;
            acc[2][0] += q2 * k0; acc[2][1] += q2 * k1; acc[2][2] += q2 * k2;
        }
        if (l < CHH) {
#pragma unroll 4
            for (int it = 0; it < 64; ++it) {
                int nn = (it + l) & 63;
                float qv = QF[g][l][nn]; nqp += qv * qv;
                float kv = KF[g][l][nn]; nkp += kv * kv;
            }
        }
        __syncthreads();
    }

#pragma unroll
    for (int a = 0; a < 3; ++a)
#pragma unroll
        for (int cc = 0; cc < 3; ++cc)
            atomicAdd(&g_gram[(bh * CHH + i0 + a) * CHH + j0 + cc], acc[a][cc]);
    if (l < CHH) {
        atomicAdd(&g_nq[b * CDIM + hd * CHH + l], nqp);
        atomicAdd(&g_nk[b * CDIM + hd * CHH + l], nkp);
    }
}

// ---------------------------------------------------------------------------
// Softmax + W_eff = W_proj @ A_blockdiag, emitted fp16 [192][192]
// ---------------------------------------------------------------------------
__global__ void softmax_weff_kernel(const float* __restrict__ temp,
                                    const float* __restrict__ Wp)
{
    const int b = blockIdx.x;
    const int t = threadIdx.x;            // 384
    __shared__ float A[HEADS][CHH][CHH];
    __shared__ float qinv[CDIM], kinv[CDIM];

    if (t < CDIM) {
        qinv[t] = 1.0f / fmaxf(sqrtf(g_nq[b * CDIM + t]), 1e-12f);
    } else if (t < 2 * CDIM) {
        int c = t - CDIM;
        kinv[c] = 1.0f / fmaxf(sqrtf(g_nk[b * CDIM + c]), 1e-12f);
    }
    __syncthreads();

    if (t < CDIM) {
        const int hd = t / CHH, i = t % CHH;
        const float tp = temp[hd];
        const float qi = qinv[hd * CHH + i];
        float row[CHH];
        float m = -1e30f;
#pragma unroll
        for (int j = 0; j < CHH; ++j) {
            float v = g_gram[((b * HEADS + hd) * CHH + i) * CHH + j]
                      * tp * qi * kinv[hd * CHH + j];
            row[j] = v;
            m = fmaxf(m, v);
        }
        float ssum = 0.f;
#pragma unroll
        for (int j = 0; j < CHH; ++j) { row[j] = expf(row[j] - m); ssum += row[j]; }
        float inv = 1.0f / ssum;
#pragma unroll
        for (int j = 0; j < CHH; ++j) A[hd][i][j] = row[j] * inv;
    }
    __syncthreads();

    for (int idx = t; idx < CDIM * CDIM; idx += 384) {
        const int o = idx / CDIM, cc = idx % CDIM;
        const int hd = cc / CHH, j = cc % CHH;
        float s = 0.f;
#pragma unroll
        for (int i = 0; i < CHH; ++i)
            s += Wp[o * CDIM + hd * CHH + i] * A[hd][i][j];
        g_weff[(long long)b * CDIM * CDIM + idx] = __float2half(s);
    }
}

// ---------------------------------------------------------------------------
extern "C" void kernel_launch(void* const* d_in, const int* in_sizes, int n_in,
                              void* d_out, int out_size)
{
    (void)in_sizes; (void)n_in; (void)out_size;
    const float* x     = (const float*)d_in[0];
    const float* feat  = (const float*)d_in[1];
    const float* Wqkv  = (const float*)d_in[2];
    const float* Wdw   = (const float*)d_in[3];
    const float* Wproj = (const float*)d_in[4];
    const float* temp  = (const float*)d_in[5];
    float* out = (float*)d_out;

    float *qkv1, *qkv2;
    __half *wq, *wf;
    cudaGetSymbolAddress((void**)&qkv1, g_qkv1);
    cudaGetSymbolAddress((void**)&qkv2, g_qkv2);
    cudaGetSymbolAddress((void**)&wq, g_wq);
    cudaGetSymbolAddress((void**)&wf, g_weff);

    static int smem_set = 0;
    if (!smem_set) {
        cudaFuncSetAttribute(gemm_mma, cudaFuncAttributeMaxDynamicSharedMemorySize,
                             SMEM_GEMM);
        smem_set = 1;
    }

    const int HALF_W = C3 * CDIM / 2;

    // Launch order puts dwconv at ncu slot 4 this round.
    prep_wqkv_kernel<<<(HALF_W + 255) / 256, 256>>>(Wqkv, 0);
    prep_wqkv_kernel<<<(HALF_W + 255) / 256, 256>>>(Wqkv, HALF_W);

    // 3) qkv1 = W_qkv @ x
    gemm_mma<<<dim3(3, NPIX / (64 * NT), BATCH), 256, SMEM_GEMM>>>(
        wq, 0LL, x, (long long)CDIM * NPIX, qkv1, (long long)C3 * NPIX);

    // 4) depthwise conv  (profiled this round)
    {
        long long total = (long long)BATCH * C3 * (NPIX / 4);
        dwconv_kernel<<<(int)((total + 255) / 256), 256>>>(qkv1, Wdw, qkv2);
    }

    // 5) zero gram/norm accumulators
    zero_misc_kernel<<<(BATCH * HEADS * CHH * CHH + 255) / 256, 256>>>();

    // 6) Gram + norms
    gram_kernel<<<dim3(16, BATCH * HEADS), 256>>>(feat);

    // 7) softmax + W_eff (fp16)
    softmax_weff_kernel<<<BATCH, 384>>>(temp, Wproj);

    // 8) out = W_eff @ v
    gemm_mma<<<dim3(1, NPIX / (64 * NT), BATCH), 256, SMEM_GEMM>>>(
        wf, (long long)CDIM * CDIM,
        qkv2 + (long long)2 * CDIM * NPIX, (long long)C3 * NPIX,
        out, (long long)CDIM * NPIX);
}

// round 11
// speedup vs baseline: 1.0391x; 1.0391x over previous
#include <cuda_runtime.h>
#include <cuda_fp16.h>
#include <math.h>
#include <stdint.h>

#define BATCH 8
#define CDIM 192
#define C3 576
#define HEADS 8
#define CHH 24
#define NPIX 16384
#define IMW 128

// ---------------- scratch (device globals; allocation-free rule) ------------
__device__ float g_qkv1[BATCH * C3 * NPIX];
__device__ float g_qkv2[BATCH * C3 * NPIX];
__device__ float g_gram[BATCH * HEADS * CHH * CHH];
__device__ float g_nq[BATCH * CDIM];
__device__ float g_nk[BATCH * CDIM];
__device__ __half g_wq[C3 * CDIM];
__device__ __half g_weff[BATCH * CDIM * CDIM];

#define MMA_F16(d, a, bb) \
    asm volatile("mma.sync.aligned.m16n8k16.row.col.f32.f16.f16.f32 " \
        "{%0,%1,%2,%3}, {%4,%5,%6,%7}, {%8,%9}, {%0,%1,%2,%3};" \
        : "+f"((d)[0]), "+f"((d)[1]), "+f"((d)[2]), "+f"((d)[3]) \
        : "r"((a)[0]), "r"((a)[1]), "r"((a)[2]), "r"((a)[3]), \
          "r"((bb)[0]), "r"((bb)[1]))

#define LDSM_X4(r0, r1, r2, r3, addr) \
    asm volatile("ldmatrix.sync.aligned.m8n8.x4.shared.b16 {%0,%1,%2,%3}, [%4];" \
        : "=r"(r0), "=r"(r1), "=r"(r2), "=r"(r3) : "r"(addr))

__device__ __forceinline__ uint32_t pack_h2(__half a, __half b) {
    return ((uint32_t)__half_as_ushort(b) << 16) | __half_as_ushort(a);
}
__device__ __forceinline__ uint32_t smem_u32(const void* p) {
    uint32_t a;
    asm("{ .reg .u64 t; cvta.to.shared.u64 t, %1; cvt.u32.u64 %0, t; }"
        : "=r"(a) : "l"(p));
    return a;
}
__device__ __forceinline__ void cp_async16(uint32_t dst, const void* src) {
    asm volatile("cp.async.cg.shared.global [%0], [%1], 16;" :: "r"(dst), "l"(src));
}

// ---------------------------------------------------------------------------
// HMMA GEMM, B-panel-stationary: block owns one 64-wide n-tile; loads the
// FULL B panel (64 n x 192 k, fp32->fp16) into smem once, then sweeps NO
// o-panels of 192 rows (A panel cp.async per panel, overlapped with previous
// epilogue). 256 threads, 8 warps 4M x 2N (48x32/warp), 2 CTAs/SM.
// ---------------------------------------------------------------------------
#define LDAE 200                       // A row stride (halves)
#define LDBF 200                       // B row stride (halves), full K + pad
#define A_BYTES (192 * LDAE * 2)       // 76800
#define SMEM_GEMM (A_BYTES + 64 * LDBF * 2)   // 102400 bytes

__global__ __launch_bounds__(256, 2)
void gemm_mma(const __half* __restrict__ W, long long wstride,
              const float* __restrict__ X, long long xstride,
              float* __restrict__ Y, long long ystride, int NO)
{
    extern __shared__ __half smem[];
    __half* Ah = smem;
    __half* Bs = smem + 192 * LDAE;

    const int b = blockIdx.y;
    const int n0 = blockIdx.x * 64;
    const __half* Wp = W + (long long)b * wstride;
    const float* Xp = X + (long long)b * xstride;
    float* Yp = Y + (long long)b * ystride;

    const int tid = threadIdx.x;
    const int lane = tid & 31;
    const int wid = tid >> 5;
    const int wm = wid & 3;            // 4 in M (48 rows each)
    const int wn = wid >> 2;           // 2 in N (32 cols each)

    const uint32_t a_base = smem_u32(Ah);
    const uint32_t b_base = smem_u32(Bs);

    // ---- issue A panel 0 (cp.async), then load full B panel ----
    {
#pragma unroll
        for (int c = 0; c < 18; ++c) {
            int ch = c * 256 + tid;            // 0..4607
            int row = ch / 24, col = ch % 24;  // 16B chunks (8 halves)
            uint32_t doff = (uint32_t)(row * LDAE + col * 8) * 2u;
            cp_async16(a_base + doff, Wp + (long long)row * CDIM + col * 8);
        }
        asm volatile("cp.async.commit_group;");
    }
    // B: 64 n x 192 k; thread task: k-pair x 4 n's; 6 tasks/thread
#pragma unroll
    for (int it = 0; it < 6; ++it) {
        int id = it * 256 + tid;           // 0..1535
        int kr = (id >> 4) * 2;            // 0..190 even
        int nc = (id & 15) * 4;
        float4 r0 = *reinterpret_cast<const float4*>(&Xp[(long long)kr * NPIX + n0 + nc]);
        float4 r1 = *reinterpret_cast<const float4*>(&Xp[(long long)(kr + 1) * NPIX + n0 + nc]);
        float e0[4] = {r0.x, r0.y, r0.z, r0.w};
        float e1[4] = {r1.x, r1.y, r1.z, r1.w};
#pragma unroll
        for (int i = 0; i < 4; ++i)
            *reinterpret_cast<uint32_t*>(&Bs[(nc + i) * LDBF + kr]) =
                pack_h2(__float2half(e0[i]), __float2half(e1[i]));
    }

    // ---- ldmatrix per-lane addresses ----
    const int lg = lane >> 3, lr = lane & 7;
    uint32_t a_row[3];
#pragma unroll
    for (int mi = 0; mi < 3; ++mi) {
        int row = wm * 48 + mi * 16 + (lg & 1) * 8 + lr;
        a_row[mi] = a_base + (uint32_t)(row * LDAE + (lg >> 1) * 8) * 2u;
    }
    uint32_t b_row[2];
#pragma unroll
    for (int nj = 0; nj < 2; ++nj) {
        int n = wn * 32 + (nj * 2 + (lg >> 1)) * 8 + lr;
        b_row[nj] = b_base + (uint32_t)(n * LDBF + (lg & 1) * 8) * 2u;
    }

    for (int op = 0; op < NO; ++op) {
        asm volatile("cp.async.wait_group 0;");
        __syncthreads();                    // A(op) + B visible; prior op done

        float acc[3][4][4];
#pragma unroll
        for (int mi = 0; mi < 3; ++mi)
#pragma unroll
            for (int ni = 0; ni < 4; ++ni)
#pragma unroll
                for (int q = 0; q < 4; ++q) acc[mi][ni][q] = 0.f;

#pragma unroll
        for (int ks = 0; ks < 12; ++ks) {
            const uint32_t koff = (uint32_t)(ks * 16) * 2u;
            uint32_t fa[3][4], fb[4][2];
#pragma unroll
            for (int mi = 0; mi < 3; ++mi)
                LDSM_X4(fa[mi][0], fa[mi][1], fa[mi][2], fa[mi][3],
                        a_row[mi] + koff);
#pragma unroll
            for (int nj = 0; nj < 2; ++nj)
                LDSM_X4(fb[2 * nj][0], fb[2 * nj][1], fb[2 * nj + 1][0], fb[2 * nj + 1][1],
                        b_row[nj] + koff);
#pragma unroll
            for (int mi = 0; mi < 3; ++mi)
#pragma unroll
                for (int ni = 0; ni < 4; ++ni)
                    MMA_F16(acc[mi][ni], fa[mi], fb[ni]);
        }

        __syncthreads();                    // all warps done reading A(op)

        // prefetch next A panel; overlaps the epilogue's global stores
        if (op + 1 < NO) {
            const __half* Wn = Wp + (long long)(op + 1) * 192 * CDIM;
#pragma unroll
            for (int c = 0; c < 18; ++c) {
                int ch = c * 256 + tid;
                int row = ch / 24, col = ch % 24;
                uint32_t doff = (uint32_t)(row * LDAE + col * 8) * 2u;
                cp_async16(a_base + doff, Wn + (long long)row * CDIM + col * 8);
            }
            asm volatile("cp.async.commit_group;");
        }

        // ---- epilogue for this o-panel ----
        const int ob = op * 192;
#pragma unroll
        for (int mi = 0; mi < 3; ++mi) {
            int r = ob + wm * 48 + mi * 16 + (lane >> 2);
#pragma unroll
            for (int ni = 0; ni < 4; ++ni) {
                int c = n0 + wn * 32 + ni * 8 + (lane & 3) * 2;
                *reinterpret_cast<float2*>(&Yp[(long long)r * NPIX + c]) =
                    make_float2(acc[mi][ni][0], acc[mi][ni][1]);
                *reinterpret_cast<float2*>(&Yp[(long long)(r + 8) * NPIX + c]) =
                    make_float2(acc[mi][ni][2], acc[mi][ni][3]);
            }
        }
    }
}

// ---------------------------------------------------------------------------
// Weight prep: fp32 -> fp16
// ---------------------------------------------------------------------------
__global__ void prep_wqkv_kernel(const float* __restrict__ W, int base)
{
    int idx = base + blockIdx.x * blockDim.x + threadIdx.x;
    if (idx >= C3 * CDIM) return;
    g_wq[idx] = __float2half(W[idx]);
}

// ---------------------------------------------------------------------------
// 3x3 depthwise conv, padding 1; 8 pixels per thread (2x float4)
// ---------------------------------------------------------------------------
__global__ void dwconv_kernel(const float* __restrict__ in,
                              const float* __restrict__ wdw,
                              float* __restrict__ out)
{
    long long idx = (long long)blockIdx.x * blockDim.x + threadIdx.x;
    if (idx >= (long long)BATCH * C3 * (NPIX / 8)) return;
    const int n8 = (int)(idx & (NPIX / 8 - 1));
    const int ch = (int)(idx >> 11);
    const int oc = ch % C3;
    const int y = n8 >> 4;
    const int x0 = (n8 & 15) * 8;
    const float* w = wdw + oc * 9;
    const float* p = in + (long long)ch * NPIX;

    float o[8];
#pragma unroll
    for (int i = 0; i < 8; ++i) o[i] = 0.f;
#pragma unroll
    for (int r = 0; r < 3; ++r) {
        int yy = y + r - 1;
        if (yy < 0 || yy > IMW - 1) continue;
        const float* row = p + yy * IMW;
        float4 c0 = *reinterpret_cast<const float4*>(&row[x0]);
        float4 c1 = *reinterpret_cast<const float4*>(&row[x0 + 4]);
        float e[10];
        e[0] = (x0 > 0) ? row[x0 - 1] : 0.f;
        e[1] = c0.x; e[2] = c0.y; e[3] = c0.z; e[4] = c0.w;
        e[5] = c1.x; e[6] = c1.y; e[7] = c1.z; e[8] = c1.w;
        e[9] = (x0 < IMW - 8) ? row[x0 + 8] : 0.f;
        float w0 = w[r * 3], w1 = w[r * 3 + 1], w2 = w[r * 3 + 2];
#pragma unroll
        for (int i = 0; i < 8; ++i)
            o[i] += w0 * e[i] + w1 * e[i + 1] + w2 * e[i + 2];
    }
    float* op = out + (long long)ch * NPIX + y * IMW + x0;
    *reinterpret_cast<float4*>(op) = make_float4(o[0], o[1], o[2], o[3]);
    *reinterpret_cast<float4*>(op + 4) = make_float4(o[4], o[5], o[6], o[7]);
}

__global__ void zero_misc_kernel()
{
    int i = blockIdx.x * blockDim.x + threadIdx.x;
    if (i < BATCH * HEADS * CHH * CHH) g_gram[i] = 0.f;
    if (i < BATCH * CDIM) { g_nq[i] = 0.f; g_nk[i] = 0.f; }
}

// ---------------------------------------------------------------------------
// Gram + fused norms
// ---------------------------------------------------------------------------
__global__ void gram_kernel(const float* __restrict__ feat)
{
    __shared__ float QF[4][CHH][64];
    __shared__ float KF[4][CHH][64];

    const int bh = blockIdx.y;
    const int b = bh >> 3, hd = bh & 7;
    const int n0 = blockIdx.x * 1024;
    const int t = threadIdx.x;
    const int g = t >> 6, l = t & 63;
    const int li = l >> 3, lj = l & 7;
    const int i0 = li * 3, j0 = lj * 3;

    const float* qbase = g_qkv2 + ((long long)b * C3 + hd * CHH) * NPIX;
    const float* kbase = g_qkv2 + ((long long)b * C3 + CDIM + hd * CHH) * NPIX;
    const float* fbase = feat + ((long long)b * CDIM + hd * CHH) * NPIX;

    float acc[3][3];
#pragma unroll
    for (int a = 0; a < 3; ++a)
#pragma unroll
        for (int cc = 0; cc < 3; ++cc) acc[a][cc] = 0.f;
    float nqp = 0.f, nkp = 0.f;

    for (int s = 0; s < 1024; s += 256) {
        const int nb = n0 + s + g * 64;
        for (int e = l; e < CHH * 64; e += 64) {
            int i = e >> 6, nn = e & 63;
            long long off = (long long)i * NPIX + nb + nn;
            float fv = fbase[off];
            QF[g][i][nn] = qbase[off] * fv;
            KF[g][i][nn] = kbase[off] * fv;
        }
        __syncthreads();
#pragma unroll 4
        for (int it = 0; it < 64; ++it) {
            int nn = (it + l) & 63;
            float q0 = QF[g][i0 + 0][nn];
            float q1 = QF[g][i0 + 1][nn];
            float q2 = QF[g][i0 + 2][nn];
            float k0 = KF[g][j0 + 0][nn];
            float k1 = KF[g][j0 + 1][nn];
            float k2 = KF[g][j0 + 2][nn];
            acc[0][0] += q0 * k0; acc[0][1] += q0 * k1; acc[0][2] += q0 * k2;
            acc[1][0] += q1 * k0; acc[1][1] += q1 * k1; acc[1][2] += q1 * k2;
            acc[2][0] += q2 * k0; acc[2][1] += q2 * k1; acc[2][2] += q2 * k2;
        }
        if (l < CHH) {
#pragma unroll 4
            for (int it = 0; it < 64; ++it) {
                int nn = (it + l) & 63;
                float qv = QF[g][l][nn]; nqp += qv * qv;
                float kv = KF[g][l][nn]; nkp += kv * kv;
            }
        }
        __syncthreads();
    }

#pragma unroll
    for (int a = 0; a < 3; ++a)
#pragma unroll
        for (int cc = 0; cc < 3; ++cc)
            atomicAdd(&g_gram[(bh * CHH + i0 + a) * CHH + j0 + cc], acc[a][cc]);
    if (l < CHH) {
        atomicAdd(&g_nq[b * CDIM + hd * CHH + l], nqp);
        atomicAdd(&g_nk[b * CDIM + hd * CHH + l], nkp);
    }
}

// ---------------------------------------------------------------------------
// Softmax + W_eff = W_proj @ A_blockdiag, emitted fp16 [192][192]
// ---------------------------------------------------------------------------
__global__ void softmax_weff_kernel(const float* __restrict__ temp,
                                    const float* __restrict__ Wp)
{
    const int b = blockIdx.x;
    const int t = threadIdx.x;            // 384
    __shared__ float A[HEADS][CHH][CHH];
    __shared__ float qinv[CDIM], kinv[CDIM];

    if (t < CDIM) {
        qinv[t] = 1.0f / fmaxf(sqrtf(g_nq[b * CDIM + t]), 1e-12f);
    } else if (t < 2 * CDIM) {
        int c = t - CDIM;
        kinv[c] = 1.0f / fmaxf(sqrtf(g_nk[b * CDIM + c]), 1e-12f);
    }
    __syncthreads();

    if (t < CDIM) {
        const int hd = t / CHH, i = t % CHH;
        const float tp = temp[hd];
        const float qi = qinv[hd * CHH + i];
        float row[CHH];
        float m = -1e30f;
#pragma unroll
        for (int j = 0; j < CHH; ++j) {
            float v = g_gram[((b * HEADS + hd) * CHH + i) * CHH + j]
                      * tp * qi * kinv[hd * CHH + j];
            row[j] = v;
            m = fmaxf(m, v);
        }
        float ssum = 0.f;
#pragma unroll
        for (int j = 0; j < CHH; ++j) { row[j] = expf(row[j] - m); ssum += row[j]; }
        float inv = 1.0f / ssum;
#pragma unroll
        for (int j = 0; j < CHH; ++j) A[hd][i][j] = row[j] * inv;
    }
    __syncthreads();

    for (int idx = t; idx < CDIM * CDIM; idx += 384) {
        const int o = idx / CDIM, cc = idx % CDIM;
        const int hd = cc / CHH, j = cc % CHH;
        float s = 0.f;
#pragma unroll
        for (int i = 0; i < CHH; ++i)
            s += Wp[o * CDIM + hd * CHH + i] * A[hd][i][j];
        g_weff[(long long)b * CDIM * CDIM + idx] = __float2half(s);
    }
}

// ---------------------------------------------------------------------------
extern "C" void kernel_launch(void* const* d_in, const int* in_sizes, int n_in,
                              void* d_out, int out_size)
{
    (void)in_sizes; (void)n_in; (void)out_size;
    const float* x     = (const float*)d_in[0];
    const float* feat  = (const float*)d_in[1];
    const float* Wqkv  = (const float*)d_in[2];
    const float* Wdw   = (const float*)d_in[3];
    const float* Wproj = (const float*)d_in[4];
    const float* temp  = (const float*)d_in[5];
    float* out = (float*)d_out;

    float *qkv1, *qkv2;
    __half *wq, *wf;
    cudaGetSymbolAddress((void**)&qkv1, g_qkv1);
    cudaGetSymbolAddress((void**)&qkv2, g_qkv2);
    cudaGetSymbolAddress((void**)&wq, g_wq);
    cudaGetSymbolAddress((void**)&wf, g_weff);

    static int smem_set = 0;
    if (!smem_set) {
        cudaFuncSetAttribute(gemm_mma, cudaFuncAttributeMaxDynamicSharedMemorySize,
                             SMEM_GEMM);
        smem_set = 1;
    }

    const int HALF_W = C3 * CDIM / 2;

    // Launch order puts gemm1 at ncu slot 4.
    zero_misc_kernel<<<(BATCH * HEADS * CHH * CHH + 255) / 256, 256>>>();
    prep_wqkv_kernel<<<(HALF_W + 255) / 256, 256>>>(Wqkv, 0);
    prep_wqkv_kernel<<<(HALF_W + 255) / 256, 256>>>(Wqkv, HALF_W);

    // 4) qkv1 = W_qkv @ x  (B-stationary, 3 o-panels per block)
    gemm_mma<<<dim3(NPIX / 64, BATCH), 256, SMEM_GEMM>>>(
        wq, 0LL, x, (long long)CDIM * NPIX, qkv1, (long long)C3 * NPIX, 3);

    // 5) depthwise conv (8 px/thread)
    {
        long long total = (long long)BATCH * C3 * (NPIX / 8);
        dwconv_kernel<<<(int)((total + 255) / 256), 256>>>(qkv1, Wdw, qkv2);
    }

    // 6) Gram + norms
    gram_kernel<<<dim3(16, BATCH * HEADS), 256>>>(feat);

    // 7) softmax + W_eff (fp16)
    softmax_weff_kernel<<<BATCH, 384>>>(temp, Wproj);

    // 8) out = W_eff @ v  (single o-panel)
    gemm_mma<<<dim3(NPIX / 64, BATCH), 256, SMEM_GEMM>>>(
        wf, (long long)CDIM * CDIM,
        qkv2 + (long long)2 * CDIM * NPIX, (long long)C3 * NPIX,
        out, (long long)CDIM * NPIX, 1);
}